// round 9
// baseline (speedup 1.0000x reference)
#include <cuda_runtime.h>

// SSIM loss, fused separable 11x11 Gaussian depthwise conv, packed f32x2 math.
// Input: img1, img2 fp32 (16,3,512,512). Output: scalar float = 1 - mean(ssim_map).

#define HH   512
#define WW   512
#define NPLANES 48           // 16 * 3
#define OUT_W 64
#define OUT_H 32
#define HALO 5
#define IN_W  (OUT_W + 2*HALO)   // 74
#define IN_WP 76                 // padded row, in float2 pairs (16B-safe)
#define IN_H  (OUT_H + 2*HALO)   // 42
#define NTHREADS 256
#define RB  4                    // register blocking, horizontal pass
#define RBV 8                    // register blocking, vertical pass

#define TOTAL_PIX (16.0 * 3.0 * 512.0 * 512.0)

typedef unsigned long long ull;

__device__ double g_accum;

// Normalized 1D Gaussian, ws=11 sigma=1.5 (matches reference to fp32 rounding).
#define GW0  0.00102838f
#define GW1  0.00759876f
#define GW2  0.03600077f
#define GW3  0.10936061f
#define GW4  0.21300553f
#define GW5  0.26601172f

// ---- packed f32x2 helpers (Blackwell FFMA2/FMUL2; ptxas only emits via PTX) ----
#define FMA2(d, a, b, c) asm("fma.rn.f32x2 %0, %1, %2, %3;" : "=l"(d) : "l"(a), "l"(b), "l"(c))
#define MUL2(d, a, b)    asm("mul.rn.f32x2 %0, %1, %2;"     : "=l"(d) : "l"(a), "l"(b))

__device__ __forceinline__ ull pk2(float lo, float hi) {
    ull r;
    asm("mov.b64 %0, {%1, %2};" : "=l"(r) : "r"(__float_as_uint(lo)), "r"(__float_as_uint(hi)));
    return r;
}
__device__ __forceinline__ float lo32(ull v) { return __uint_as_float((unsigned)v); }
__device__ __forceinline__ float hi32(ull v) { return __uint_as_float((unsigned)(v >> 32)); }

__device__ __forceinline__ float clip01(float v) {
    // fmaxf(NaN, 0) -> 0, so this is nan_to_num + clip in two ops
    return fminf(fmaxf(v, 0.0f), 1.0f);
}

__global__ void zero_kernel() { g_accum = 0.0; }

__global__ void fin_kernel(float* __restrict__ out) {
    out[0] = (float)(1.0 - g_accum * (1.0 / TOTAL_PIX));
}

// smem float offsets
#define S12_OFF   0                                  // [IN_H][IN_WP] float2
#define HS01_OFF  (IN_H * IN_WP * 2)                 // [IN_H][OUT_W] float2 (mu1h, mu2h)
#define HS23_OFF  (HS01_OFF + IN_H * OUT_W * 2)      // [IN_H][OUT_W] float2 (x1x1h, x2x2h)
#define HS12_OFF  (HS23_OFF + IN_H * OUT_W * 2)      // [IN_H][OUT_W] float  (x1x2h)
#define SMEM_FLOATS (HS12_OFF + IN_H * OUT_W)        // 19824 floats = 79296 B

__global__ void __launch_bounds__(NTHREADS, 2)
ssim_kernel(const float* __restrict__ img1, const float* __restrict__ img2)
{
    const float GW[11]  = {GW0, GW1, GW2, GW3, GW4, GW5, GW4, GW3, GW2, GW1, GW0};
    const ull   GW2P[11] = {pk2(GW0,GW0), pk2(GW1,GW1), pk2(GW2,GW2), pk2(GW3,GW3),
                            pk2(GW4,GW4), pk2(GW5,GW5), pk2(GW4,GW4), pk2(GW3,GW3),
                            pk2(GW2,GW2), pk2(GW1,GW1), pk2(GW0,GW0)};   // 6 distinct after CSE

    extern __shared__ float sm[];
    float2* s12  = reinterpret_cast<float2*>(sm + S12_OFF);
    float2* hs01 = reinterpret_cast<float2*>(sm + HS01_OFF);
    float2* hs23 = reinterpret_cast<float2*>(sm + HS23_OFF);
    float*  hs12 = sm + HS12_OFF;

    const int tid = threadIdx.x;
    const int p   = blockIdx.z;
    const int x0  = blockIdx.x * OUT_W;
    const int y0  = blockIdx.y * OUT_H;
    const float* base1 = img1 + (size_t)p * HH * WW;
    const float* base2 = img2 + (size_t)p * HH * WW;

    const bool interior = (x0 >= HALO) && (x0 + OUT_W + HALO <= WW) &&
                          (y0 >= HALO) && (y0 + OUT_H + HALO <= HH);

    // ---- Phase 1: load halo tiles, interleaved (img1,img2) pairs ----
    // Scalar global loads only: x0-HALO is odd for interior tiles, wide LDG would fault.
    if (interior) {
        const float* b1 = base1 + (y0 - HALO) * WW + (x0 - HALO);
        const float* b2 = base2 + (y0 - HALO) * WW + (x0 - HALO);
        #pragma unroll 4
        for (int idx = tid; idx < IN_H * IN_W; idx += NTHREADS) {
            int r = idx / IN_W;
            int c = idx - r * IN_W;
            int gi = r * WW + c;
            s12[r * IN_WP + c] = make_float2(clip01(b1[gi]), clip01(b2[gi]));
        }
    } else {
        #pragma unroll 4
        for (int idx = tid; idx < IN_H * IN_W; idx += NTHREADS) {
            int r = idx / IN_W;
            int c = idx - r * IN_W;
            int gy = y0 - HALO + r;
            int gx = x0 - HALO + c;
            float v1 = 0.0f, v2 = 0.0f;
            if (gy >= 0 && gy < HH && gx >= 0 && gx < WW) {
                int gi = gy * WW + gx;
                v1 = clip01(base1[gi]);
                v2 = clip01(base2[gi]);
            }
            s12[r * IN_WP + c] = make_float2(v1, v2);
        }
    }
    __syncthreads();

    // ---- Phase 2: horizontal 11-tap pass, packed pairs, RB=4 outputs/thread ----
    // 42 rows * 16 groups = 672 work items.
    for (int g = tid; g < IN_H * (OUT_W / RB); g += NTHREADS) {
        int r = g >> 4;                // / (OUT_W/RB)=16
        int x = (g & 15) * RB;

        // 16 packed (x1,x2) pairs; need indices 0..13, load 16 for 16B-aligned LDS.128
        ull v[16];
        {
            const ulonglong2* row = reinterpret_cast<const ulonglong2*>(s12 + r * IN_WP + x);
            #pragma unroll
            for (int i = 0; i < 8; i++) {
                ulonglong2 t = row[i];
                v[2*i]   = t.x;
                v[2*i+1] = t.y;
            }
        }

        ull pm[RB], ps[RB];            // (mu1,mu2) and (x1x1,x2x2) packed accumulators
        float c12[RB];                 // cross x1*x2 accumulator (scalar)
        #pragma unroll
        for (int o = 0; o < RB; o++) { pm[o] = 0ull; ps[o] = 0ull; c12[o] = 0.0f; }

        #pragma unroll
        for (int k = 0; k < 11; k++) {
            #pragma unroll
            for (int o = 0; o < RB; o++) {
                ull x12 = v[k + o];
                ull m12;
                MUL2(m12, GW2P[k], x12);           // (w*x1, w*x2)
                FMA2(pm[o], GW2P[k], x12, pm[o]);  // mu pair
                FMA2(ps[o], m12, x12, ps[o]);      // squares pair
                c12[o] = fmaf(lo32(m12), hi32(x12), c12[o]);  // w*x1*x2 (lanes = free)
            }
        }

        int ro = r * OUT_W + x;
        ulonglong2* o01 = reinterpret_cast<ulonglong2*>(hs01 + ro);
        ulonglong2* o23 = reinterpret_cast<ulonglong2*>(hs23 + ro);
        o01[0] = make_ulonglong2(pm[0], pm[1]);
        o01[1] = make_ulonglong2(pm[2], pm[3]);
        o23[0] = make_ulonglong2(ps[0], ps[1]);
        o23[1] = make_ulonglong2(ps[2], ps[3]);
        *reinterpret_cast<float4*>(hs12 + ro) = make_float4(c12[0], c12[1], c12[2], c12[3]);
    }
    __syncthreads();

    // ---- Phase 3: vertical 11-tap pass + SSIM, RBV=8 rows/thread ----
    // 64 cols * 4 row-groups = 256 items = exactly one per thread.
    float lsum = 0.0f;
    {
        int x = tid & 63;
        int y = (tid >> 6) * RBV;

        ull bm[RBV], bsq[RBV];
        float b12[RBV];
        #pragma unroll
        for (int o = 0; o < RBV; o++) { bm[o] = 0ull; bsq[o] = 0ull; b12[o] = 0.0f; }

        const float2* p01 = hs01 + y * OUT_W + x;
        const float2* p23 = hs23 + y * OUT_W + x;
        const float*  p12 = hs12 + y * OUT_W + x;

        #pragma unroll
        for (int rr = 0; rr < 10 + RBV; rr++) {
            ull h01 = *reinterpret_cast<const ull*>(p01 + rr * OUT_W);   // LDS.64
            ull h23 = *reinterpret_cast<const ull*>(p23 + rr * OUT_W);   // LDS.64
            float h12 = p12[rr * OUT_W];                                  // LDS.32
            #pragma unroll
            for (int o = 0; o < RBV; o++) {
                int k = rr - o;                   // compile-time per unrolled instance
                if (k >= 0 && k < 11) {
                    FMA2(bm[o],  GW2P[k], h01, bm[o]);
                    FMA2(bsq[o], GW2P[k], h23, bsq[o]);
                    b12[o] = fmaf(GW[k], h12, b12[o]);   // FFMA-imm
                }
            }
        }

        const float C1 = 0.000101f;   // 0.01^2 + 1e-6
        const float C2 = 0.000901f;   // 0.03^2 + 1e-6
        #pragma unroll
        for (int o = 0; o < RBV; o++) {
            float mu1 = lo32(bm[o]),  mu2 = hi32(bm[o]);
            float e11 = lo32(bsq[o]), e22 = hi32(bsq[o]);
            float mu1sq = mu1 * mu1;
            float mu2sq = mu2 * mu2;
            float mu12  = mu1 * mu2;
            float sig1  = fminf(fmaxf(e11 - mu1sq, 1e-6f), 1e6f);
            float sig2  = fminf(fmaxf(e22 - mu2sq, 1e-6f), 1e6f);
            float sig12 = b12[o] - mu12;
            float num = (2.0f * mu12 + C1) * (2.0f * sig12 + C2);
            float den = (mu1sq + mu2sq + C1) * (sig1 + sig2 + C2);
            lsum += __fdividef(num, den);   // den >= C1*C2 > 0, always finite
        }
    }

    // ---- block reduction -> one double atomic per block ----
    #pragma unroll
    for (int s = 16; s > 0; s >>= 1)
        lsum += __shfl_xor_sync(0xffffffffu, lsum, s);

    __shared__ float red[NTHREADS / 32];
    if ((tid & 31) == 0) red[tid >> 5] = lsum;
    __syncthreads();
    if (tid == 0) {
        float bs = 0.0f;
        #pragma unroll
        for (int i = 0; i < NTHREADS / 32; i++) bs += red[i];
        atomicAdd(&g_accum, (double)bs);
    }
}

extern "C" void kernel_launch(void* const* d_in, const int* in_sizes, int n_in,
                              void* d_out, int out_size)
{
    const float* img1 = (const float*)d_in[0];
    const float* img2 = (const float*)d_in[1];
    float* out = (float*)d_out;

    const size_t smem = (size_t)SMEM_FLOATS * sizeof(float);   // 79296 B
    cudaFuncSetAttribute(ssim_kernel, cudaFuncAttributeMaxDynamicSharedMemorySize, (int)smem);

    zero_kernel<<<1, 1>>>();
    dim3 grid(WW / OUT_W, HH / OUT_H, NPLANES);   // 8 x 16 x 48
    ssim_kernel<<<grid, NTHREADS, smem>>>(img1, img2);
    fin_kernel<<<1, 1>>>(out);
}